// round 10
// baseline (speedup 1.0000x reference)
#include <cuda_runtime.h>
#include <math.h>

#define A_COUNT 1024
#define DFEAT   128
#define NTOTAL  524288

// eps = 1e-4 / D
#define EPS (7.8125e-7f)

// rows per warp
#define RPW 8
#define BLOCK_THREADS 256
#define WARPS_PER_BLOCK (BLOCK_THREADS / 32)
#define ROWS_PER_BLOCK (WARPS_PER_BLOCK * RPW)   // 64
#define GRID_BLOCKS (NTOTAL / ROWS_PER_BLOCK)    // 8192

// Zero at module load; the last finishing block resets them after use, so
// every graph replay (and the first correctness call) starts from zeros.
__device__ __align__(16) float g_per_anchor[A_COUNT];
__device__ unsigned int g_done;

// Release atomic: orders this block's prior (lane-0 RED) atomics before the
// counter bump WITHOUT a GPU-scope fence (no CCTL.IVALL, no bulk drain).
__device__ __forceinline__ unsigned atom_add_release_gpu(unsigned* p, unsigned v) {
    unsigned old;
    asm volatile("atom.add.release.gpu.u32 %0, [%1], %2;"
                 : "=r"(old) : "l"(p), "r"(v) : "memory");
    return old;
}

__global__ __launch_bounds__(BLOCK_THREADS)
void dist_kernel(const float* __restrict__ anchors,
                 const float* __restrict__ X,
                 const int*   __restrict__ seg,
                 float*       __restrict__ out) {
    const int lane = threadIdx.x & 31;
    const int warp = threadIdx.x >> 5;
    const int base = (blockIdx.x * WARPS_PER_BLOCK + warp) * RPW;

    // Per-lane float4 covers the whole 128-float row: lane*4 .. lane*4+3.
    const float4* __restrict__ X4 = reinterpret_cast<const float4*>(X);
    const float4* __restrict__ A4 = reinterpret_cast<const float4*>(anchors);

    int   cur_seg = seg[base];
    float4 a = A4[(size_t)cur_seg * (DFEAT / 4) + lane];
    float4 x = X4[(size_t)base * (DFEAT / 4) + lane];

    float acc = 0.0f;   // only lane 0's value matters

    #pragma unroll
    for (int r = 0; r < RPW; r++) {
        const int row = base + r;

        // Prefetch next row's data before consuming current (MLP>=2 per warp,
        // interleaved — keep MLP_p1 low to avoid L1tex-queue spread).
        float4 x_next;
        int    s_next = cur_seg;
        if (r + 1 < RPW) {
            s_next = seg[row + 1];
            x_next = X4[(size_t)(row + 1) * (DFEAT / 4) + lane];
        }

        float d0 = x.x - a.x;
        float d1 = x.y - a.y;
        float d2 = x.z - a.z;
        float d3 = x.w - a.w;
        float ss = d0 * d0 + d1 * d1 + d2 * d2 + d3 * d3;

        #pragma unroll
        for (int off = 16; off; off >>= 1)
            ss += __shfl_xor_sync(0xffffffffu, ss, off);

        if (lane == 0) acc += sqrtf(ss + EPS);

        if (r + 1 < RPW) {
            if (s_next != cur_seg) {
                // Segment boundary (warp-uniform): flush and reload anchor.
                if (lane == 0) {
                    atomicAdd(&g_per_anchor[cur_seg], acc);
                    acc = 0.0f;
                }
                cur_seg = s_next;
                a = A4[(size_t)cur_seg * (DFEAT / 4) + lane];
            }
            x = x_next;
        }
    }

    if (lane == 0) atomicAdd(&g_per_anchor[cur_seg], acc);

    // ---- fused finalize: last block does the log1p reduction ----
    __shared__ bool is_last;
    __shared__ float sdata[WARPS_PER_BLOCK];
    __syncthreads();                       // all lane-0 REDs issued
    if (threadIdx.x == 0)
        is_last = (atom_add_release_gpu(&g_done, 1u) == GRID_BLOCKS - 1);
    __syncthreads();
    if (!is_last) return;

    __threadfence();                       // acquire side (single block, once)

    // 256 threads, one float4 (4 anchors) each.
    float4* pa4 = reinterpret_cast<float4*>(g_per_anchor);
    const float4* pa4c = reinterpret_cast<const float4*>(g_per_anchor);
    float4 p = __ldcg(&pa4c[threadIdx.x]);           // L2 read, sees all REDs
    pa4[threadIdx.x] = make_float4(0.f, 0.f, 0.f, 0.f);  // reset for replay

    float v = log1pf(p.x) + log1pf(p.y) + log1pf(p.z) + log1pf(p.w);

    #pragma unroll
    for (int off = 16; off; off >>= 1)
        v += __shfl_xor_sync(0xffffffffu, v, off);
    if (lane == 0) sdata[warp] = v;
    __syncthreads();

    if (threadIdx.x == 0) {
        float w = 0.0f;
        #pragma unroll
        for (int i = 0; i < WARPS_PER_BLOCK; i++) w += sdata[i];
        out[0] = w / (float)NTOTAL;
        g_done = 0u;                       // reset counter for next replay
    }
}

extern "C" void kernel_launch(void* const* d_in, const int* in_sizes, int n_in,
                              void* d_out, int out_size) {
    const float* anchors = (const float*)d_in[0];   // [A, D]
    const float* Xn_flat = (const float*)d_in[1];   // [TOTAL, D]
    const int*   seg     = (const int*)d_in[2];     // [TOTAL]
    float* out = (float*)d_out;

    dist_kernel<<<GRID_BLOCKS, BLOCK_THREADS>>>(anchors, Xn_flat, seg, out);
}

// round 11
// speedup vs baseline: 1.2086x; 1.2086x over previous
#include <cuda_runtime.h>
#include <math.h>

#define A_COUNT 1024
#define DFEAT   128
#define NTOTAL  524288

// eps = 1e-4 / D
#define EPS (7.8125e-7f)

// rows per warp
#define RPW 8
#define BLOCK_THREADS 256
#define WARPS_PER_BLOCK (BLOCK_THREADS / 32)
#define ROWS_PER_BLOCK (WARPS_PER_BLOCK * RPW)   // 64
#define GRID_BLOCKS (NTOTAL / ROWS_PER_BLOCK)    // 8192

// Zero at module load; finalize_kernel resets it after reading, so every
// graph replay (and the first correctness call) sees zeros. No init kernel.
__device__ __align__(16) float g_per_anchor[A_COUNT];

__device__ __forceinline__ void cp_async16(void* smem_dst, const void* gsrc) {
    unsigned s = (unsigned)__cvta_generic_to_shared(smem_dst);
    asm volatile("cp.async.cg.shared.global [%0], [%1], 16;"
                 :: "r"(s), "l"(gsrc) : "memory");
}
__device__ __forceinline__ void cp_async_commit() {
    asm volatile("cp.async.commit_group;" ::: "memory");
}
__device__ __forceinline__ void cp_async_wait_all() {
    asm volatile("cp.async.wait_group 0;" ::: "memory");
}

__global__ __launch_bounds__(BLOCK_THREADS)
void dist_kernel(const float* __restrict__ anchors,
                 const float* __restrict__ X,
                 const int*   __restrict__ seg) {
    // 8 warps x 8 rows x 32 lanes x 16B = 32 KB -> 7 CTAs/SM.
    __shared__ float4 xs[WARPS_PER_BLOCK][RPW][32];

    const int lane = threadIdx.x & 31;
    const int warp = threadIdx.x >> 5;
    const int base = (blockIdx.x * WARPS_PER_BLOCK + warp) * RPW;

    const float4* __restrict__ X4 = reinterpret_cast<const float4*>(X);
    const float4* __restrict__ A4 = reinterpret_cast<const float4*>(anchors);

    // Stage all 8 rows via cp.async (no register destination -> ptxas cannot
    // serialize; 8 independent 512B row-loads in flight per warp, L1-bypass).
    #pragma unroll
    for (int r = 0; r < RPW; r++)
        cp_async16(&xs[warp][r][lane],
                   &X4[(size_t)(base + r) * (DFEAT / 4) + lane]);
    cp_async_commit();

    // Overlap: segment ids (uniform broadcast) + first anchor row.
    int s[RPW];
    #pragma unroll
    for (int r = 0; r < RPW; r++) s[r] = seg[base + r];

    int   cur_seg = s[0];
    float4 a = A4[(size_t)cur_seg * (DFEAT / 4) + lane];

    cp_async_wait_all();
    __syncwarp();

    float acc = 0.0f;   // only lane 0's value matters

    #pragma unroll
    for (int r = 0; r < RPW; r++) {
        float4 x = xs[warp][r][lane];    // LDS.128, conflict-free

        float d0 = x.x - a.x;
        float d1 = x.y - a.y;
        float d2 = x.z - a.z;
        float d3 = x.w - a.w;
        float ss = d0 * d0 + d1 * d1 + d2 * d2 + d3 * d3;

        #pragma unroll
        for (int off = 16; off; off >>= 1)
            ss += __shfl_xor_sync(0xffffffffu, ss, off);

        if (lane == 0) acc += sqrtf(ss + EPS);

        if (r + 1 < RPW) {
            if (s[r + 1] != cur_seg) {
                // Segment boundary (warp-uniform): flush and reload anchor.
                if (lane == 0) {
                    atomicAdd(&g_per_anchor[cur_seg], acc);
                    acc = 0.0f;
                }
                cur_seg = s[r + 1];
                a = A4[(size_t)cur_seg * (DFEAT / 4) + lane];
            }
        }
    }

    if (lane == 0) atomicAdd(&g_per_anchor[cur_seg], acc);
}

// Lean finalize: 256 threads, one float4 (4 anchors) per thread, one barrier.
__global__ __launch_bounds__(256)
void finalize_kernel(float* __restrict__ out) {
    __shared__ float sdata[8];
    const int tid  = threadIdx.x;
    const int lane = tid & 31;
    const int warp = tid >> 5;

    float4* pa4 = reinterpret_cast<float4*>(g_per_anchor);
    float4 p = pa4[tid];                       // LDG.128, 256 in flight
    pa4[tid] = make_float4(0.f, 0.f, 0.f, 0.f);  // reset for next replay

    float v = log1pf(p.x) + log1pf(p.y) + log1pf(p.z) + log1pf(p.w);

    #pragma unroll
    for (int off = 16; off; off >>= 1)
        v += __shfl_xor_sync(0xffffffffu, v, off);
    if (lane == 0) sdata[warp] = v;
    __syncthreads();

    if (tid == 0) {
        float w = 0.0f;
        #pragma unroll
        for (int i = 0; i < 8; i++) w += sdata[i];
        out[0] = w / (float)NTOTAL;
    }
}

extern "C" void kernel_launch(void* const* d_in, const int* in_sizes, int n_in,
                              void* d_out, int out_size) {
    const float* anchors = (const float*)d_in[0];   // [A, D]
    const float* Xn_flat = (const float*)d_in[1];   // [TOTAL, D]
    const int*   seg     = (const int*)d_in[2];     // [TOTAL]
    float* out = (float*)d_out;

    dist_kernel<<<GRID_BLOCKS, BLOCK_THREADS>>>(anchors, Xn_flat, seg);

    finalize_kernel<<<1, 256>>>(out);
}